// round 16
// baseline (speedup 1.0000x reference)
#include <cuda_runtime.h>
#include <math.h>

#define BN 2
#define HH 256
#define WWD 256
#define CC 64
#define PIXB (HH*WWD)
#define NPIX (BN*PIXB)
#define NCHUNK 512

// ---------------- device scratch ----------------
__device__ float g_v [NPIX*CC];
__device__ float g_m1[NPIX*CC];
__device__ float g_m2[NPIX*CC];
__device__ float g_t1[NPIX*CC];
__device__ float g_t2[NPIX*CC];
__device__ float g_gpart[NCHUNK*4096];
__device__ float g_gpart2[32*4096];
__device__ float g_wfold[BN*4096];
__device__ float g_w2f[4096];
__device__ float g_b2f[64];

__device__ __forceinline__ float sigmf(float x) {
    return 1.0f / (1.0f + __expf(-x));
}
__device__ __forceinline__ float geluf(float v) {
    return 0.5f * v * (1.0f + erff(v * 0.70710678118654752f));
}

// ---------------- fused: Gram partials (symmetric) + v = Wv * x ----------------
__global__ __launch_bounds__(256) void k_gramv(const float* __restrict__ x,
                                               const float* __restrict__ Wv)
{
    __shared__ float sx[8][64];
    __shared__ float sW[64*68];
    int chunk = blockIdx.x;
    int base  = chunk * 256;
    int tid = threadIdx.x;
    int row = tid & 63;
    int pxg = tid >> 6;

    for (int t = tid; t < 4096; t += 256) sW[(t >> 6)*68 + (t & 63)] = Wv[t];
    __syncthreads();
    float w[64];
    #pragma unroll
    for (int k = 0; k < 16; k++) {
        float4 a = *(const float4*)&sW[row*68 + 4*k];
        w[4*k+0]=a.x; w[4*k+1]=a.y; w[4*k+2]=a.z; w[4*k+3]=a.w;
    }

    bool active = tid < 136;
    int ti = 0, rem = active ? tid : 0;
    if (active) { while (rem >= 16 - ti) { rem -= 16 - ti; ti++; } }
    int tj = ti + rem;

    float a00=0,a01=0,a02=0,a03=0, a10=0,a11=0,a12=0,a13=0;
    float a20=0,a21=0,a22=0,a23=0, a30=0,a31=0,a32=0,a33=0;

    for (int pp = 0; pp < 256; pp += 8) {
        __syncthreads();
        int idx = tid * 2;
        int pr = idx >> 6, cc = idx & 63;
        float2 v2 = *(const float2*)&x[(size_t)(base + pp + pr)*CC + cc];
        sx[pr][cc] = v2.x; sx[pr][cc+1] = v2.y;
        __syncthreads();
        if (active) {
            #pragma unroll
            for (int p = 0; p < 8; p++) {
                float4 xi = *(const float4*)&sx[p][4*ti];
                float4 xj = *(const float4*)&sx[p][4*tj];
                a00 += xi.x*xj.x; a01 += xi.x*xj.y; a02 += xi.x*xj.z; a03 += xi.x*xj.w;
                a10 += xi.y*xj.x; a11 += xi.y*xj.y; a12 += xi.y*xj.z; a13 += xi.y*xj.w;
                a20 += xi.z*xj.x; a21 += xi.z*xj.y; a22 += xi.z*xj.z; a23 += xi.z*xj.w;
                a30 += xi.w*xj.x; a31 += xi.w*xj.y; a32 += xi.w*xj.z; a33 += xi.w*xj.w;
            }
        }
        {
            int lp0 = pxg*2, lp1 = pxg*2 + 1;
            float v0 = 0.f, v1 = 0.f;
            #pragma unroll
            for (int c = 0; c < 64; c += 4) {
                float4 xa = *(const float4*)&sx[lp0][c];
                float4 xb = *(const float4*)&sx[lp1][c];
                v0 = fmaf(w[c+0], xa.x, v0); v0 = fmaf(w[c+1], xa.y, v0);
                v0 = fmaf(w[c+2], xa.z, v0); v0 = fmaf(w[c+3], xa.w, v0);
                v1 = fmaf(w[c+0], xb.x, v1); v1 = fmaf(w[c+1], xb.y, v1);
                v1 = fmaf(w[c+2], xb.z, v1); v1 = fmaf(w[c+3], xb.w, v1);
            }
            g_v[(size_t)(base + pp + lp0)*64 + row] = v0;
            g_v[(size_t)(base + pp + lp1)*64 + row] = v1;
        }
    }
    if (active) {
        float* dst = &g_gpart[(size_t)chunk*4096];
        int r = 4*ti, c = 4*tj;
        dst[(r+0)*64+c+0]=a00; dst[(r+0)*64+c+1]=a01; dst[(r+0)*64+c+2]=a02; dst[(r+0)*64+c+3]=a03;
        dst[(r+1)*64+c+0]=a10; dst[(r+1)*64+c+1]=a11; dst[(r+1)*64+c+2]=a12; dst[(r+1)*64+c+3]=a13;
        dst[(r+2)*64+c+0]=a20; dst[(r+2)*64+c+1]=a21; dst[(r+2)*64+c+2]=a22; dst[(r+2)*64+c+3]=a23;
        dst[(r+3)*64+c+0]=a30; dst[(r+3)*64+c+1]=a31; dst[(r+3)*64+c+2]=a32; dst[(r+3)*64+c+3]=a33;
        if (ti != tj) {
            dst[(c+0)*64+r+0]=a00; dst[(c+1)*64+r+0]=a01; dst[(c+2)*64+r+0]=a02; dst[(c+3)*64+r+0]=a03;
            dst[(c+0)*64+r+1]=a10; dst[(c+1)*64+r+1]=a11; dst[(c+2)*64+r+1]=a12; dst[(c+3)*64+r+1]=a13;
            dst[(c+0)*64+r+2]=a20; dst[(c+1)*64+r+2]=a21; dst[(c+2)*64+r+2]=a22; dst[(c+3)*64+r+2]=a23;
            dst[(c+0)*64+r+3]=a30; dst[(c+1)*64+r+3]=a31; dst[(c+2)*64+r+3]=a32; dst[(c+3)*64+r+3]=a33;
        }
    }
}

__global__ void k_gram_red1()
{
    int e = blockIdx.x*blockDim.x + threadIdx.x;
    if (e >= 32*4096) return;
    int part = e >> 12, i = e & 4095;
    float s = 0.f;
    #pragma unroll
    for (int c = 0; c < 16; c++)
        s += g_gpart[(size_t)(part*16 + c)*4096 + i];
    g_gpart2[e] = s;
}

// ---------------- fold W2*W1 (16 blocks); b2f parallel ----------------
__global__ __launch_bounds__(256) void k_fold16(const float* __restrict__ W1,
                                                const float* __restrict__ b1,
                                                const float* __restrict__ W2,
                                                const float* __restrict__ b2)
{
    __shared__ float sW1[4096];
    __shared__ float sW2r[4*64];
    __shared__ float sPart[256];
    int tid = threadIdx.x;
    for (int t = tid; t < 4096; t += 256) sW1[t] = W1[t];
    int obase = blockIdx.x * 4;
    for (int t = tid; t < 4*64; t += 256) sW2r[t] = W2[obase*64 + t];

    if (blockIdx.x == 0) {
        int o = tid >> 2, part = tid & 3;
        float p = 0.f;
        #pragma unroll
        for (int i = part*16; i < part*16 + 16; i++)
            p = fmaf(W2[o*64 + i], b1[i], p);
        sPart[tid] = p;
    }
    __syncthreads();

    int t = blockIdx.x*256 + tid;
    int o = t >> 6, c = t & 63;
    float s = 0.f;
    #pragma unroll 8
    for (int i = 0; i < 64; i++) s += sW2r[(o - obase)*64 + i] * sW1[i*64+c];
    g_w2f[t] = s;

    if (blockIdx.x == 0 && tid < 64)
        g_b2f[tid] = b2[tid] + sPart[4*tid] + sPart[4*tid+1] + sPart[4*tid+2] + sPart[4*tid+3];
}

// ---------------- tiny solve, bank-conflict-free ----------------
#define SP 65
__global__ __launch_bounds__(256) void k_small4(const float* __restrict__ Wq,
                                                const float* __restrict__ Wk,
                                                const float* __restrict__ Wp,
                                                const float* __restrict__ rs)
{
    extern __shared__ float dyn[];
    float* sG   = dyn;
    float* sGq  = dyn + 4160;
    float* sW   = dyn + 8320;
    float* sLog = dyn + 12480;
    float* sNq  = dyn + 13504;
    float* sNk  = dyn + 13568;
    float* sPart= dyn + 13632;
    int b = blockIdx.x;
    int tid = threadIdx.x;

    for (int t = tid; t < 4096; t += 256) {
        float s = 0.f;
        #pragma unroll
        for (int c = 0; c < 16; c++)
            s += g_gpart2[(size_t)(b*16 + c)*4096 + t];
        sG[(t >> 6)*SP + (t & 63)] = s;
        sW[(t >> 6)*SP + (t & 63)] = Wq[t];
    }
    __syncthreads();
    for (int t = tid; t < 4096; t += 256) {
        int c = t >> 6, o = t & 63;
        float s0 = 0.f, s1 = 0.f, s2 = 0.f, s3 = 0.f;
        #pragma unroll
        for (int i = 0; i < 64; i += 4) {
            s0 = fmaf(sG[c*SP+i+0], sW[o*SP+i+0], s0);
            s1 = fmaf(sG[c*SP+i+1], sW[o*SP+i+1], s1);
            s2 = fmaf(sG[c*SP+i+2], sW[o*SP+i+2], s2);
            s3 = fmaf(sG[c*SP+i+3], sW[o*SP+i+3], s3);
        }
        sGq[c*SP+o] = (s0+s1) + (s2+s3);
    }
    __syncthreads();
    if (tid < 64) {
        int o = tid;
        float qq = 0.f;
        #pragma unroll 8
        for (int c = 0; c < 64; c++) qq += sW[o*SP+c] * sGq[c*SP+o];
        sNq[o] = fmaxf(sqrtf(fmaxf(qq, 0.f)), 1e-12f);
    }
    __syncthreads();
    for (int t = tid; t < 4096; t += 256) sW[(t >> 6)*SP + (t & 63)] = Wk[t];
    __syncthreads();
    {
        int o = tid >> 2, part = tid & 3;
        float kp = 0.f;
        for (int c = part*16; c < part*16 + 16; c++) {
            float g0 = 0.f, g1 = 0.f, g2 = 0.f, g3 = 0.f;
            #pragma unroll
            for (int i = 0; i < 64; i += 4) {
                g0 = fmaf(sG[c*SP+i+0], sW[o*SP+i+0], g0);
                g1 = fmaf(sG[c*SP+i+1], sW[o*SP+i+1], g1);
                g2 = fmaf(sG[c*SP+i+2], sW[o*SP+i+2], g2);
                g3 = fmaf(sG[c*SP+i+3], sW[o*SP+i+3], g3);
            }
            kp = fmaf(sW[o*SP+c], (g0+g1)+(g2+g3), kp);
        }
        sPart[tid] = kp;
    }
    __syncthreads();
    if (tid < 64) {
        float kk = sPart[4*tid] + sPart[4*tid+1] + sPart[4*tid+2] + sPart[4*tid+3];
        sNk[tid] = fmaxf(sqrtf(fmaxf(kk, 0.f)), 1e-12f);
    }
    __syncthreads();
    for (int t = tid; t < 1024; t += 256) {
        int h = t >> 8, d = (t >> 4) & 15, e = t & 15;
        int rk = h*16 + d, rq = h*16 + e;
        float s0 = 0.f, s1 = 0.f, s2 = 0.f, s3 = 0.f;
        #pragma unroll
        for (int c = 0; c < 64; c += 4) {
            s0 = fmaf(sW[rk*SP+c+0], sGq[(c+0)*SP+rq], s0);
            s1 = fmaf(sW[rk*SP+c+1], sGq[(c+1)*SP+rq], s1);
            s2 = fmaf(sW[rk*SP+c+2], sGq[(c+2)*SP+rq], s2);
            s3 = fmaf(sW[rk*SP+c+3], sGq[(c+3)*SP+rq], s3);
        }
        sLog[t] = ((s0+s1)+(s2+s3)) / (sNk[rk] * sNq[rq]) * rs[h];
    }
    __syncthreads();
    if (tid < 64) {
        float* row = &sLog[tid*16];
        float m = row[0];
        for (int e = 1; e < 16; e++) m = fmaxf(m, row[e]);
        float sum = 0.f;
        for (int e = 0; e < 16; e++) { float ev = expf(row[e]-m); row[e] = ev; sum += ev; }
        float inv = 1.f / sum;
        for (int e = 0; e < 16; e++) row[e] *= inv;
    }
    __syncthreads();
    for (int t = tid; t < 4096; t += 256) sW[(t >> 6)*SP + (t & 63)] = Wp[t];
    __syncthreads();
    for (int t = tid; t < 4096; t += 256) {
        int o = t >> 6, j = t & 63, hj = j >> 4, ej = j & 15;
        float s = 0.f;
        #pragma unroll
        for (int d = 0; d < 16; d++)
            s += sW[o*SP + hj*16 + d] * sLog[(hj*16 + d)*16 + ej];
        g_wfold[b*4096 + t] = s;
    }
}

// ---------------- dual matvec: m1 = W1*mask + b1 ; m2 = W2f*mask + b2f ----------------
__global__ __launch_bounds__(512) void k_mv_dual(const float* __restrict__ mask,
                                                 const float* __restrict__ W1,
                                                 const float* __restrict__ b1)
{
    __shared__ float4 sx4[2048];
    float* sx = (float*)sx4;
    int tid = threadIdx.x, lane = tid & 31, wid = tid >> 5;
    int mat = wid >> 3;
    int row = ((wid >> 2) & 1)*32 + lane;

    for (int t = tid; t < 4096; t += 512) sx[(t >> 6)*68 + (t & 63)] = W1[t];
    __syncthreads();
    float w[64];
    if (mat == 0) {
        #pragma unroll
        for (int k = 0; k < 16; k++) {
            float4 a = *(const float4*)&sx[row*68 + 4*k];
            w[4*k+0]=a.x; w[4*k+1]=a.y; w[4*k+2]=a.z; w[4*k+3]=a.w;
        }
    }
    __syncthreads();
    for (int t = tid; t < 4096; t += 512) sx[(t >> 6)*68 + (t & 63)] = g_w2f[t];
    __syncthreads();
    if (mat == 1) {
        #pragma unroll
        for (int k = 0; k < 16; k++) {
            float4 a = *(const float4*)&sx[row*68 + 4*k];
            w[4*k+0]=a.x; w[4*k+1]=a.y; w[4*k+2]=a.z; w[4*k+3]=a.w;
        }
    }
    float bb = (mat == 0) ? b1[row] : g_b2f[row];
    __syncthreads();

    size_t pbase = (size_t)blockIdx.x * 128;
    const float4* in4 = (const float4*)mask + pbase*16;
    #pragma unroll
    for (int j = 0; j < 4; j++) sx4[tid + 512*j] = in4[tid + 512*j];
    __syncthreads();

    float* dst = (mat == 0) ? g_m1 : g_m2;
    int pw = (wid & 3) * 32;
    #pragma unroll 2
    for (int q = 0; q < 8; q++) {
        int p0 = pw + q*4;
        float a0 = bb, a1 = bb, a2 = bb, a3 = bb;
        #pragma unroll
        for (int k4 = 0; k4 < 16; k4++) {
            float4 x0 = *(const float4*)&sx[(p0+0)*64 + 4*k4];
            float4 x1 = *(const float4*)&sx[(p0+1)*64 + 4*k4];
            float4 x2 = *(const float4*)&sx[(p0+2)*64 + 4*k4];
            float4 x3 = *(const float4*)&sx[(p0+3)*64 + 4*k4];
            a0 = fmaf(w[4*k4+0], x0.x, a0); a0 = fmaf(w[4*k4+1], x0.y, a0);
            a0 = fmaf(w[4*k4+2], x0.z, a0); a0 = fmaf(w[4*k4+3], x0.w, a0);
            a1 = fmaf(w[4*k4+0], x1.x, a1); a1 = fmaf(w[4*k4+1], x1.y, a1);
            a1 = fmaf(w[4*k4+2], x1.z, a1); a1 = fmaf(w[4*k4+3], x1.w, a1);
            a2 = fmaf(w[4*k4+0], x2.x, a2); a2 = fmaf(w[4*k4+1], x2.y, a2);
            a2 = fmaf(w[4*k4+2], x2.z, a2); a2 = fmaf(w[4*k4+3], x2.w, a2);
            a3 = fmaf(w[4*k4+0], x3.x, a3); a3 = fmaf(w[4*k4+1], x3.y, a3);
            a3 = fmaf(w[4*k4+2], x3.z, a3); a3 = fmaf(w[4*k4+3], x3.w, a3);
        }
        size_t o0 = (pbase + p0)*64 + row;
        dst[o0]     = a0;
        dst[o0+64]  = a1;
        dst[o0+128] = a2;
        dst[o0+192] = a3;
    }
}

// ---------------- dwconv, 4-pixel strips ----------------
__global__ __launch_bounds__(256) void k_pe1_s(const float* __restrict__ x,
                                               const float* __restrict__ w)
{
    __shared__ float sw[9*CC];
    for (int t = threadIdx.x; t < 9*CC; t += 256) { int c = t/9, k = t%9; sw[k*CC+c] = w[t]; }
    __syncthreads();
    int g = threadIdx.x & 15, strip = threadIdx.x >> 4;
    int pbase = blockIdx.x*64 + strip*4;
    int b = pbase >> 16, s = pbase & 65535, y = s >> 8, x0 = s & 255;
    const float4* x4 = (const float4*)x;
    const float4* sw4 = (const float4*)sw;
    float4 acc[4];
    #pragma unroll
    for (int p = 0; p < 4; p++) acc[p] = make_float4(0.f,0.f,0.f,0.f);
    size_t bb = (size_t)(b << 16);
    #pragma unroll
    for (int ky = 0; ky < 3; ky++) {
        int yy = y + ky - 1; if (yy < 0 || yy >= HH) continue;
        #pragma unroll
        for (int c = -1; c <= 4; c++) {
            int xc = x0 + c; if (xc < 0 || xc >= WWD) continue;
            float4 v = x4[(bb + (yy<<8) + xc)*16 + g];
            #pragma unroll
            for (int p = 0; p < 4; p++) {
                int kx = c - p + 1; if (kx < 0 || kx > 2) continue;
                float4 wv = sw4[(ky*3+kx)*16 + g];
                acc[p].x = fmaf(wv.x, v.x, acc[p].x); acc[p].y = fmaf(wv.y, v.y, acc[p].y);
                acc[p].z = fmaf(wv.z, v.z, acc[p].z); acc[p].w = fmaf(wv.w, v.w, acc[p].w);
            }
        }
    }
    float4* t14 = (float4*)g_t1;
    #pragma unroll
    for (int p = 0; p < 4; p++) {
        float4 r;
        r.x = geluf(acc[p].x); r.y = geluf(acc[p].y);
        r.z = geluf(acc[p].z); r.w = geluf(acc[p].w);
        t14[(size_t)(pbase+p)*16 + g] = r;
    }
}

__global__ __launch_bounds__(256) void k_pe2_s(const float* __restrict__ w)
{
    __shared__ float sw[9*CC];
    for (int t = threadIdx.x; t < 9*CC; t += 256) { int c = t/9, k = t%9; sw[k*CC+c] = w[t]; }
    __syncthreads();
    int g = threadIdx.x & 15, strip = threadIdx.x >> 4;
    int pbase = blockIdx.x*64 + strip*4;
    int b = pbase >> 16, s = pbase & 65535, y = s >> 8, x0 = s & 255;
    const float4* t14 = (const float4*)g_t1;
    const float4* sw4 = (const float4*)sw;
    float4 acc[4];
    #pragma unroll
    for (int p = 0; p < 4; p++) acc[p] = make_float4(0.f,0.f,0.f,0.f);
    size_t bb = (size_t)(b << 16);
    #pragma unroll
    for (int ky = 0; ky < 3; ky++) {
        int yy = y + ky - 1; if (yy < 0 || yy >= HH) continue;
        #pragma unroll
        for (int c = -1; c <= 4; c++) {
            int xc = x0 + c; if (xc < 0 || xc >= WWD) continue;
            float4 v = t14[(bb + (yy<<8) + xc)*16 + g];
            #pragma unroll
            for (int p = 0; p < 4; p++) {
                int kx = c - p + 1; if (kx < 0 || kx > 2) continue;
                float4 wv = sw4[(ky*3+kx)*16 + g];
                acc[p].x = fmaf(wv.x, v.x, acc[p].x); acc[p].y = fmaf(wv.y, v.y, acc[p].y);
                acc[p].z = fmaf(wv.z, v.z, acc[p].z); acc[p].w = fmaf(wv.w, v.w, acc[p].w);
            }
        }
    }
    float4* t24 = (float4*)g_t2;
    #pragma unroll
    for (int p = 0; p < 4; p++) t24[(size_t)(pbase+p)*16 + g] = acc[p];
}

// ---------------- fused final: gate (dw5x5 + m1*v) -> smem ; folded matvec + t2 ----------------
// dyn smem floats: sW[4352] sVM[8192] sdw[1600] sdb[64] = 14208 (56832 B)
__global__ __launch_bounds__(256) void k_finalf(const float* __restrict__ bp,
                                                const float* __restrict__ dw,
                                                const float* __restrict__ dwb,
                                                float* __restrict__ out)
{
    extern __shared__ float fs[];
    float* sW  = fs;
    float* sVM = fs + 4352;
    float* sdw = fs + 12544;
    float* sdb = fs + 14144;

    int tid = threadIdx.x, lane = tid & 31, wid = tid >> 5;
    size_t pbase = (size_t)blockIdx.x * 128;
    int b = (int)(pbase >> 16);
    int sb = (int)(pbase & 65535);
    int y = sb >> 8, x0b = sb & 255;
    size_t bbase = (size_t)b << 16;

    const float* Wf = g_wfold + b*4096;
    for (int t = tid; t < 4096; t += 256) sW[(t >> 6)*68 + (t & 63)] = Wf[t];
    for (int t = tid; t < 25*CC; t += 256) { int c = t/25, k = t%25; sdw[k*CC+c] = dw[t]; }
    if (tid < 64) sdb[tid] = dwb[tid];
    __syncthreads();

    // phase A: gate -> sVM (512 tasks: 32 strips x 16 channel groups)
    const float4* m24 = (const float4*)g_m2;
    const float4* m14 = (const float4*)g_m1;
    const float4* v4  = (const float4*)g_v;
    const float4* sdw4 = (const float4*)sdw;
    float4* sVM4 = (float4*)sVM;
    #pragma unroll
    for (int t = tid; t < 512; t += 256) {
        int strip = t >> 4, g = t & 15;
        int px0 = x0b + strip*4;
        float4 bias4 = ((const float4*)sdb)[g];
        float4 acc[4];
        #pragma unroll
        for (int p = 0; p < 4; p++) acc[p] = bias4;
        #pragma unroll
        for (int ky = 0; ky < 5; ky++) {
            int yy = y + ky - 2; if (yy < 0 || yy >= HH) continue;
            #pragma unroll
            for (int c = -2; c <= 5; c++) {
                int xc = px0 + c; if (xc < 0 || xc >= WWD) continue;
                float4 v = m24[(bbase + (yy<<8) + xc)*16 + g];
                #pragma unroll
                for (int p = 0; p < 4; p++) {
                    int kx = c - p + 2; if (kx < 0 || kx > 4) continue;
                    float4 wv = sdw4[(ky*5+kx)*16 + g];
                    acc[p].x = fmaf(wv.x, v.x, acc[p].x); acc[p].y = fmaf(wv.y, v.y, acc[p].y);
                    acc[p].z = fmaf(wv.z, v.z, acc[p].z); acc[p].w = fmaf(wv.w, v.w, acc[p].w);
                }
            }
        }
        #pragma unroll
        for (int p = 0; p < 4; p++) {
            size_t gi = (pbase + strip*4 + p)*16 + g;
            float4 m1v = m14[gi], vv = v4[gi];
            float4 r;
            r.x = vv.x * (m1v.x * (1.f + sigmf(acc[p].x)));
            r.y = vv.y * (m1v.y * (1.f + sigmf(acc[p].y)));
            r.z = vv.z * (m1v.z * (1.f + sigmf(acc[p].z)));
            r.w = vv.w * (m1v.w * (1.f + sigmf(acc[p].w)));
            sVM4[(strip*4 + p)*16 + g] = r;
        }
    }
    __syncthreads();

    // phase C: folded matvec from sVM (+bp, +t2)
    int row = (wid >> 2)*32 + lane;
    float w[64];
    #pragma unroll
    for (int k = 0; k < 16; k++) {
        float4 a = *(const float4*)&sW[row*68 + 4*k];
        w[4*k+0]=a.x; w[4*k+1]=a.y; w[4*k+2]=a.z; w[4*k+3]=a.w;
    }
    float bb = bp[row];
    const float* t2 = g_t2;
    int pw = (wid & 3) * 32;
    #pragma unroll 2
    for (int q = 0; q < 8; q++) {
        int p0 = pw + q*4;
        float a0 = bb, a1 = bb, a2 = bb, a3 = bb;
        #pragma unroll
        for (int k4 = 0; k4 < 16; k4++) {
            float4 x0 = *(const float4*)&sVM[(p0+0)*64 + 4*k4];
            float4 x1 = *(const float4*)&sVM[(p0+1)*64 + 4*k4];
            float4 x2 = *(const float4*)&sVM[(p0+2)*64 + 4*k4];
            float4 x3 = *(const float4*)&sVM[(p0+3)*64 + 4*k4];
            a0 = fmaf(w[4*k4+0], x0.x, a0); a0 = fmaf(w[4*k4+1], x0.y, a0);
            a0 = fmaf(w[4*k4+2], x0.z, a0); a0 = fmaf(w[4*k4+3], x0.w, a0);
            a1 = fmaf(w[4*k4+0], x1.x, a1); a1 = fmaf(w[4*k4+1], x1.y, a1);
            a1 = fmaf(w[4*k4+2], x1.z, a1); a1 = fmaf(w[4*k4+3], x1.w, a1);
            a2 = fmaf(w[4*k4+0], x2.x, a2); a2 = fmaf(w[4*k4+1], x2.y, a2);
            a2 = fmaf(w[4*k4+2], x2.z, a2); a2 = fmaf(w[4*k4+3], x2.w, a2);
            a3 = fmaf(w[4*k4+0], x3.x, a3); a3 = fmaf(w[4*k4+1], x3.y, a3);
            a3 = fmaf(w[4*k4+2], x3.z, a3); a3 = fmaf(w[4*k4+3], x3.w, a3);
        }
        size_t o0 = (pbase + p0)*64 + row;
        a0 += t2[o0]; a1 += t2[o0+64]; a2 += t2[o0+128]; a3 += t2[o0+192];
        out[o0]     = a0;
        out[o0+64]  = a1;
        out[o0+128] = a2;
        out[o0+192] = a3;
    }
}

// ---------------- launcher ----------------
extern "C" void kernel_launch(void* const* d_in, const int* in_sizes, int n_in,
                              void* d_out, int out_size)
{
    const float* x_in   = (const float*)d_in[0];
    const float* mask   = (const float*)d_in[1];
    const float* Wq     = (const float*)d_in[2];
    const float* Wk     = (const float*)d_in[3];
    const float* Wv     = (const float*)d_in[4];
    const float* rescale= (const float*)d_in[5];
    const float* Wp     = (const float*)d_in[6];
    const float* bp     = (const float*)d_in[7];
    const float* mm_w1  = (const float*)d_in[8];
    const float* mm_b1  = (const float*)d_in[9];
    const float* mm_w2  = (const float*)d_in[10];
    const float* mm_b2  = (const float*)d_in[11];
    const float* mm_dw  = (const float*)d_in[12];
    const float* mm_dwb = (const float*)d_in[13];
    const float* pe_w1  = (const float*)d_in[14];
    const float* pe_w2  = (const float*)d_in[15];
    float* out = (float*)d_out;

    const int SM4_BYTES = (4160*3 + 1024 + 64 + 64 + 256) * 4;
    const int KF_BYTES  = 14208 * 4;   // 56832

    static cudaStream_t s1 = nullptr, s2 = nullptr;
    static cudaEvent_t evRoot = nullptr, evM = nullptr, evP = nullptr;
    static int init_done = 0;
    if (!init_done) {
        cudaFuncSetAttribute(k_small4, cudaFuncAttributeMaxDynamicSharedMemorySize, SM4_BYTES);
        cudaFuncSetAttribute(k_finalf, cudaFuncAttributeMaxDynamicSharedMemorySize, KF_BYTES);
        cudaStreamCreateWithFlags(&s1, cudaStreamNonBlocking);
        cudaStreamCreateWithFlags(&s2, cudaStreamNonBlocking);
        cudaEventCreateWithFlags(&evRoot, cudaEventDisableTiming);
        cudaEventCreateWithFlags(&evM,    cudaEventDisableTiming);
        cudaEventCreateWithFlags(&evP,    cudaEventDisableTiming);
        init_done = 1;
    }

    bool multi = (s1 && s2 && evRoot && evM && evP);

    if (multi) {
        cudaEventRecord(evRoot, 0);
        cudaStreamWaitEvent(s1, evRoot, 0);
        cudaStreamWaitEvent(s2, evRoot, 0);

        // stream 0: fused gram+v, gram chain
        k_gramv<<<NCHUNK, 256>>>(x_in, Wv);
        k_gram_red1<<<(32*4096)/256, 256>>>();
        k_small4<<<BN, 256, SM4_BYTES>>>(Wq, Wk, Wp, rescale);

        // s1: mask path (m1, m2)
        k_fold16<<<16, 256, 0, s1>>>(mm_w1, mm_b1, mm_w2, mm_b2);
        k_mv_dual<<<NPIX/128, 512, 0, s1>>>(mask, mm_w1, mm_b1);
        cudaEventRecord(evM, s1);

        // s2: pe path
        k_pe1_s<<<NPIX/64, 256, 0, s2>>>(x_in, pe_w1);
        k_pe2_s<<<NPIX/64, 256, 0, s2>>>(pe_w2);
        cudaEventRecord(evP, s2);

        // join: finalf needs v+wfold (stream-0 ordered), m1/m2 (evM), t2 (evP)
        cudaStreamWaitEvent(0, evM, 0);
        cudaStreamWaitEvent(0, evP, 0);
        k_finalf<<<NPIX/128, 256, KF_BYTES>>>(bp, mm_dw, mm_dwb, out);
    } else {
        k_fold16<<<16, 256>>>(mm_w1, mm_b1, mm_w2, mm_b2);
        k_gramv<<<NCHUNK, 256>>>(x_in, Wv);
        k_gram_red1<<<(32*4096)/256, 256>>>();
        k_small4<<<BN, 256, SM4_BYTES>>>(Wq, Wk, Wp, rescale);
        k_mv_dual<<<NPIX/128, 512>>>(mask, mm_w1, mm_b1);
        k_pe1_s<<<NPIX/64, 256>>>(x_in, pe_w1);
        k_pe2_s<<<NPIX/64, 256>>>(pe_w2);
        k_finalf<<<NPIX/128, 256, KF_BYTES>>>(bp, mm_dw, mm_dwb, out);
    }
}

// round 17
// speedup vs baseline: 1.1145x; 1.1145x over previous
#include <cuda_runtime.h>
#include <math.h>

#define BN 2
#define HH 256
#define WWD 256
#define CC 64
#define PIXB (HH*WWD)
#define NPIX (BN*PIXB)
#define NCHUNK 512

// ---------------- device scratch ----------------
__device__ float g_v [NPIX*CC];
__device__ float g_m1[NPIX*CC];
__device__ float g_m2[NPIX*CC];
__device__ float g_t1[NPIX*CC];
__device__ float g_t2[NPIX*CC];
__device__ float g_vm[NPIX*CC];
__device__ float g_gpart[NCHUNK*4096];
__device__ float g_gpart2[32*4096];
__device__ float g_wfold[BN*4096];
__device__ float g_w2f[4096];
__device__ float g_b2f[64];

__device__ __forceinline__ float sigmf(float x) {
    return 1.0f / (1.0f + __expf(-x));
}
__device__ __forceinline__ float geluf(float v) {
    return 0.5f * v * (1.0f + erff(v * 0.70710678118654752f));
}

// ---------------- fused: Gram partials (symmetric) + v = Wv * x ----------------
// block = 256 thr, chunk = 256 px. x staged once per 8-px slice, feeds both.
__global__ __launch_bounds__(256) void k_gramv(const float* __restrict__ x,
                                               const float* __restrict__ Wv)
{
    __shared__ float sx[8][64];
    __shared__ float sW[64*68];
    int chunk = blockIdx.x;
    int base  = chunk * 256;
    int tid = threadIdx.x;
    int row = tid & 63;           // v output row for this thread
    int pxg = tid >> 6;           // pixel-pair group 0..3

    // stage Wv (pad-68), coalesced, then own row -> regs
    for (int t = tid; t < 4096; t += 256) sW[(t >> 6)*68 + (t & 63)] = Wv[t];
    __syncthreads();
    float w[64];
    #pragma unroll
    for (int k = 0; k < 16; k++) {
        float4 a = *(const float4*)&sW[row*68 + 4*k];
        w[4*k+0]=a.x; w[4*k+1]=a.y; w[4*k+2]=a.z; w[4*k+3]=a.w;
    }

    // gram: threads 0..135 own upper-triangle 4x4 tiles
    bool active = tid < 136;
    int ti = 0, rem = active ? tid : 0;
    if (active) { while (rem >= 16 - ti) { rem -= 16 - ti; ti++; } }
    int tj = ti + rem;

    float a00=0,a01=0,a02=0,a03=0, a10=0,a11=0,a12=0,a13=0;
    float a20=0,a21=0,a22=0,a23=0, a30=0,a31=0,a32=0,a33=0;

    for (int pp = 0; pp < 256; pp += 8) {
        __syncthreads();
        int idx = tid * 2;
        int pr = idx >> 6, cc = idx & 63;
        float2 v2 = *(const float2*)&x[(size_t)(base + pp + pr)*CC + cc];
        sx[pr][cc] = v2.x; sx[pr][cc+1] = v2.y;
        __syncthreads();
        if (active) {
            #pragma unroll
            for (int p = 0; p < 8; p++) {
                float4 xi = *(const float4*)&sx[p][4*ti];
                float4 xj = *(const float4*)&sx[p][4*tj];
                a00 += xi.x*xj.x; a01 += xi.x*xj.y; a02 += xi.x*xj.z; a03 += xi.x*xj.w;
                a10 += xi.y*xj.x; a11 += xi.y*xj.y; a12 += xi.y*xj.z; a13 += xi.y*xj.w;
                a20 += xi.z*xj.x; a21 += xi.z*xj.y; a22 += xi.z*xj.z; a23 += xi.z*xj.w;
                a30 += xi.w*xj.x; a31 += xi.w*xj.y; a32 += xi.w*xj.z; a33 += xi.w*xj.w;
            }
        }
        // v for the 2 pixels this thread owns in this slice (smem broadcast)
        {
            int lp0 = pxg*2, lp1 = pxg*2 + 1;
            float v0 = 0.f, v1 = 0.f;
            #pragma unroll
            for (int c = 0; c < 64; c += 4) {
                float4 xa = *(const float4*)&sx[lp0][c];
                float4 xb = *(const float4*)&sx[lp1][c];
                v0 = fmaf(w[c+0], xa.x, v0); v0 = fmaf(w[c+1], xa.y, v0);
                v0 = fmaf(w[c+2], xa.z, v0); v0 = fmaf(w[c+3], xa.w, v0);
                v1 = fmaf(w[c+0], xb.x, v1); v1 = fmaf(w[c+1], xb.y, v1);
                v1 = fmaf(w[c+2], xb.z, v1); v1 = fmaf(w[c+3], xb.w, v1);
            }
            g_v[(size_t)(base + pp + lp0)*64 + row] = v0;
            g_v[(size_t)(base + pp + lp1)*64 + row] = v1;
        }
    }
    if (active) {
        float* dst = &g_gpart[(size_t)chunk*4096];
        int r = 4*ti, c = 4*tj;
        dst[(r+0)*64+c+0]=a00; dst[(r+0)*64+c+1]=a01; dst[(r+0)*64+c+2]=a02; dst[(r+0)*64+c+3]=a03;
        dst[(r+1)*64+c+0]=a10; dst[(r+1)*64+c+1]=a11; dst[(r+1)*64+c+2]=a12; dst[(r+1)*64+c+3]=a13;
        dst[(r+2)*64+c+0]=a20; dst[(r+2)*64+c+1]=a21; dst[(r+2)*64+c+2]=a22; dst[(r+2)*64+c+3]=a23;
        dst[(r+3)*64+c+0]=a30; dst[(r+3)*64+c+1]=a31; dst[(r+3)*64+c+2]=a32; dst[(r+3)*64+c+3]=a33;
        if (ti != tj) {
            dst[(c+0)*64+r+0]=a00; dst[(c+1)*64+r+0]=a01; dst[(c+2)*64+r+0]=a02; dst[(c+3)*64+r+0]=a03;
            dst[(c+0)*64+r+1]=a10; dst[(c+1)*64+r+1]=a11; dst[(c+2)*64+r+1]=a12; dst[(c+3)*64+r+1]=a13;
            dst[(c+0)*64+r+2]=a20; dst[(c+1)*64+r+2]=a21; dst[(c+2)*64+r+2]=a22; dst[(c+3)*64+r+2]=a23;
            dst[(c+0)*64+r+3]=a30; dst[(c+1)*64+r+3]=a31; dst[(c+2)*64+r+3]=a32; dst[(c+3)*64+r+3]=a33;
        }
    }
}

__global__ void k_gram_red1()
{
    int e = blockIdx.x*blockDim.x + threadIdx.x;
    if (e >= 32*4096) return;
    int part = e >> 12, i = e & 4095;
    float s = 0.f;
    #pragma unroll
    for (int c = 0; c < 16; c++)
        s += g_gpart[(size_t)(part*16 + c)*4096 + i];
    g_gpart2[e] = s;
}

// ---------------- fold W2*W1 (16 blocks); b2f parallel ----------------
__global__ __launch_bounds__(256) void k_fold16(const float* __restrict__ W1,
                                                const float* __restrict__ b1,
                                                const float* __restrict__ W2,
                                                const float* __restrict__ b2)
{
    __shared__ float sW1[4096];
    __shared__ float sW2r[4*64];
    __shared__ float sPart[256];
    int tid = threadIdx.x;
    for (int t = tid; t < 4096; t += 256) sW1[t] = W1[t];
    int obase = blockIdx.x * 4;
    for (int t = tid; t < 4*64; t += 256) sW2r[t] = W2[obase*64 + t];

    if (blockIdx.x == 0) {
        int o = tid >> 2, part = tid & 3;
        float p = 0.f;
        #pragma unroll
        for (int i = part*16; i < part*16 + 16; i++)
            p = fmaf(W2[o*64 + i], b1[i], p);
        sPart[tid] = p;
    }
    __syncthreads();

    int t = blockIdx.x*256 + tid;
    int o = t >> 6, c = t & 63;
    float s = 0.f;
    #pragma unroll 8
    for (int i = 0; i < 64; i++) s += sW2r[(o - obase)*64 + i] * sW1[i*64+c];
    g_w2f[t] = s;

    if (blockIdx.x == 0 && tid < 64)
        g_b2f[tid] = b2[tid] + sPart[4*tid] + sPart[4*tid+1] + sPart[4*tid+2] + sPart[4*tid+3];
}

// ---------------- tiny solve, bank-conflict-free (stride-65 panes) ----------------
#define SP 65
__global__ __launch_bounds__(256) void k_small4(const float* __restrict__ Wq,
                                                const float* __restrict__ Wk,
                                                const float* __restrict__ Wp,
                                                const float* __restrict__ rs)
{
    extern __shared__ float dyn[];
    float* sG   = dyn;
    float* sGq  = dyn + 4160;
    float* sW   = dyn + 8320;
    float* sLog = dyn + 12480;
    float* sNq  = dyn + 13504;
    float* sNk  = dyn + 13568;
    float* sPart= dyn + 13632;
    int b = blockIdx.x;
    int tid = threadIdx.x;

    for (int t = tid; t < 4096; t += 256) {
        float s = 0.f;
        #pragma unroll
        for (int c = 0; c < 16; c++)
            s += g_gpart2[(size_t)(b*16 + c)*4096 + t];
        sG[(t >> 6)*SP + (t & 63)] = s;
        sW[(t >> 6)*SP + (t & 63)] = Wq[t];
    }
    __syncthreads();
    for (int t = tid; t < 4096; t += 256) {
        int c = t >> 6, o = t & 63;
        float s0 = 0.f, s1 = 0.f, s2 = 0.f, s3 = 0.f;
        #pragma unroll
        for (int i = 0; i < 64; i += 4) {
            s0 = fmaf(sG[c*SP+i+0], sW[o*SP+i+0], s0);
            s1 = fmaf(sG[c*SP+i+1], sW[o*SP+i+1], s1);
            s2 = fmaf(sG[c*SP+i+2], sW[o*SP+i+2], s2);
            s3 = fmaf(sG[c*SP+i+3], sW[o*SP+i+3], s3);
        }
        sGq[c*SP+o] = (s0+s1) + (s2+s3);
    }
    __syncthreads();
    if (tid < 64) {
        int o = tid;
        float qq = 0.f;
        #pragma unroll 8
        for (int c = 0; c < 64; c++) qq += sW[o*SP+c] * sGq[c*SP+o];
        sNq[o] = fmaxf(sqrtf(fmaxf(qq, 0.f)), 1e-12f);
    }
    __syncthreads();
    for (int t = tid; t < 4096; t += 256) sW[(t >> 6)*SP + (t & 63)] = Wk[t];
    __syncthreads();
    {
        int o = tid >> 2, part = tid & 3;
        float kp = 0.f;
        for (int c = part*16; c < part*16 + 16; c++) {
            float g0 = 0.f, g1 = 0.f, g2 = 0.f, g3 = 0.f;
            #pragma unroll
            for (int i = 0; i < 64; i += 4) {
                g0 = fmaf(sG[c*SP+i+0], sW[o*SP+i+0], g0);
                g1 = fmaf(sG[c*SP+i+1], sW[o*SP+i+1], g1);
                g2 = fmaf(sG[c*SP+i+2], sW[o*SP+i+2], g2);
                g3 = fmaf(sG[c*SP+i+3], sW[o*SP+i+3], g3);
            }
            kp = fmaf(sW[o*SP+c], (g0+g1)+(g2+g3), kp);
        }
        sPart[tid] = kp;
    }
    __syncthreads();
    if (tid < 64) {
        float kk = sPart[4*tid] + sPart[4*tid+1] + sPart[4*tid+2] + sPart[4*tid+3];
        sNk[tid] = fmaxf(sqrtf(fmaxf(kk, 0.f)), 1e-12f);
    }
    __syncthreads();
    for (int t = tid; t < 1024; t += 256) {
        int h = t >> 8, d = (t >> 4) & 15, e = t & 15;
        int rk = h*16 + d, rq = h*16 + e;
        float s0 = 0.f, s1 = 0.f, s2 = 0.f, s3 = 0.f;
        #pragma unroll
        for (int c = 0; c < 64; c += 4) {
            s0 = fmaf(sW[rk*SP+c+0], sGq[(c+0)*SP+rq], s0);
            s1 = fmaf(sW[rk*SP+c+1], sGq[(c+1)*SP+rq], s1);
            s2 = fmaf(sW[rk*SP+c+2], sGq[(c+2)*SP+rq], s2);
            s3 = fmaf(sW[rk*SP+c+3], sGq[(c+3)*SP+rq], s3);
        }
        sLog[t] = ((s0+s1)+(s2+s3)) / (sNk[rk] * sNq[rq]) * rs[h];
    }
    __syncthreads();
    if (tid < 64) {
        float* row = &sLog[tid*16];
        float m = row[0];
        for (int e = 1; e < 16; e++) m = fmaxf(m, row[e]);
        float sum = 0.f;
        for (int e = 0; e < 16; e++) { float ev = expf(row[e]-m); row[e] = ev; sum += ev; }
        float inv = 1.f / sum;
        for (int e = 0; e < 16; e++) row[e] *= inv;
    }
    __syncthreads();
    for (int t = tid; t < 4096; t += 256) sW[(t >> 6)*SP + (t & 63)] = Wp[t];
    __syncthreads();
    for (int t = tid; t < 4096; t += 256) {
        int o = t >> 6, j = t & 63, hj = j >> 4, ej = j & 15;
        float s = 0.f;
        #pragma unroll
        for (int d = 0; d < 16; d++)
            s += sW[o*SP + hj*16 + d] * sLog[(hj*16 + d)*16 + ej];
        g_wfold[b*4096 + t] = s;
    }
}

// ---------------- matvec, one W-row per lane ----------------
__global__ __launch_bounds__(256) void k_mv_b(const float* __restrict__ in,
                                              const float* __restrict__ Wg,
                                              const float* __restrict__ bias,
                                              const float* __restrict__ add,
                                              float* __restrict__ out,
                                              int wsel)
{
    __shared__ float4 sx4[2048];
    float* sx = (float*)sx4;
    int tid = threadIdx.x, lane = tid & 31, wid = tid >> 5;
    int row = (wid >> 2)*32 + lane;
    const float* W = Wg + (wsel ? (int)(blockIdx.x >> 9) * 4096 : 0);

    for (int t = tid; t < 4096; t += 256) sx[(t >> 6)*68 + (t & 63)] = W[t];
    __syncthreads();
    float w[64];
    #pragma unroll
    for (int k = 0; k < 16; k++) {
        float4 a = *(const float4*)&sx[row*68 + 4*k];
        w[4*k+0]=a.x; w[4*k+1]=a.y; w[4*k+2]=a.z; w[4*k+3]=a.w;
    }
    float bb = bias ? bias[row] : 0.f;
    __syncthreads();

    size_t pbase = (size_t)blockIdx.x * 128;
    const float4* in4 = (const float4*)in + pbase*16;
    #pragma unroll
    for (int j = 0; j < 8; j++) sx4[tid + 256*j] = in4[tid + 256*j];
    __syncthreads();

    int pw = (wid & 3) * 32;
    #pragma unroll 2
    for (int q = 0; q < 8; q++) {
        int p0 = pw + q*4;
        float a0 = bb, a1 = bb, a2 = bb, a3 = bb;
        #pragma unroll
        for (int k4 = 0; k4 < 16; k4++) {
            float4 x0 = *(const float4*)&sx[(p0+0)*64 + 4*k4];
            float4 x1 = *(const float4*)&sx[(p0+1)*64 + 4*k4];
            float4 x2 = *(const float4*)&sx[(p0+2)*64 + 4*k4];
            float4 x3 = *(const float4*)&sx[(p0+3)*64 + 4*k4];
            a0 = fmaf(w[4*k4+0], x0.x, a0); a0 = fmaf(w[4*k4+1], x0.y, a0);
            a0 = fmaf(w[4*k4+2], x0.z, a0); a0 = fmaf(w[4*k4+3], x0.w, a0);
            a1 = fmaf(w[4*k4+0], x1.x, a1); a1 = fmaf(w[4*k4+1], x1.y, a1);
            a1 = fmaf(w[4*k4+2], x1.z, a1); a1 = fmaf(w[4*k4+3], x1.w, a1);
            a2 = fmaf(w[4*k4+0], x2.x, a2); a2 = fmaf(w[4*k4+1], x2.y, a2);
            a2 = fmaf(w[4*k4+2], x2.z, a2); a2 = fmaf(w[4*k4+3], x2.w, a2);
            a3 = fmaf(w[4*k4+0], x3.x, a3); a3 = fmaf(w[4*k4+1], x3.y, a3);
            a3 = fmaf(w[4*k4+2], x3.z, a3); a3 = fmaf(w[4*k4+3], x3.w, a3);
        }
        size_t o0 = (pbase + p0)*64 + row;
        if (add) {
            a0 += add[o0]; a1 += add[o0+64]; a2 += add[o0+128]; a3 += add[o0+192];
        }
        out[o0]     = a0;
        out[o0+64]  = a1;
        out[o0+128] = a2;
        out[o0+192] = a3;
    }
}

// ---------------- dual matvec: m1 = W1*mask + b1 ; m2 = W2f*mask + b2f ----------------
__global__ __launch_bounds__(512) void k_mv_dual(const float* __restrict__ mask,
                                                 const float* __restrict__ W1,
                                                 const float* __restrict__ b1)
{
    __shared__ float4 sx4[2048];
    float* sx = (float*)sx4;
    int tid = threadIdx.x, lane = tid & 31, wid = tid >> 5;
    int mat = wid >> 3;
    int row = ((wid >> 2) & 1)*32 + lane;

    for (int t = tid; t < 4096; t += 512) sx[(t >> 6)*68 + (t & 63)] = W1[t];
    __syncthreads();
    float w[64];
    if (mat == 0) {
        #pragma unroll
        for (int k = 0; k < 16; k++) {
            float4 a = *(const float4*)&sx[row*68 + 4*k];
            w[4*k+0]=a.x; w[4*k+1]=a.y; w[4*k+2]=a.z; w[4*k+3]=a.w;
        }
    }
    __syncthreads();
    for (int t = tid; t < 4096; t += 512) sx[(t >> 6)*68 + (t & 63)] = g_w2f[t];
    __syncthreads();
    if (mat == 1) {
        #pragma unroll
        for (int k = 0; k < 16; k++) {
            float4 a = *(const float4*)&sx[row*68 + 4*k];
            w[4*k+0]=a.x; w[4*k+1]=a.y; w[4*k+2]=a.z; w[4*k+3]=a.w;
        }
    }
    float bb = (mat == 0) ? b1[row] : g_b2f[row];
    __syncthreads();

    size_t pbase = (size_t)blockIdx.x * 128;
    const float4* in4 = (const float4*)mask + pbase*16;
    #pragma unroll
    for (int j = 0; j < 4; j++) sx4[tid + 512*j] = in4[tid + 512*j];
    __syncthreads();

    float* dst = (mat == 0) ? g_m1 : g_m2;
    int pw = (wid & 3) * 32;
    #pragma unroll 2
    for (int q = 0; q < 8; q++) {
        int p0 = pw + q*4;
        float a0 = bb, a1 = bb, a2 = bb, a3 = bb;
        #pragma unroll
        for (int k4 = 0; k4 < 16; k4++) {
            float4 x0 = *(const float4*)&sx[(p0+0)*64 + 4*k4];
            float4 x1 = *(const float4*)&sx[(p0+1)*64 + 4*k4];
            float4 x2 = *(const float4*)&sx[(p0+2)*64 + 4*k4];
            float4 x3 = *(const float4*)&sx[(p0+3)*64 + 4*k4];
            a0 = fmaf(w[4*k4+0], x0.x, a0); a0 = fmaf(w[4*k4+1], x0.y, a0);
            a0 = fmaf(w[4*k4+2], x0.z, a0); a0 = fmaf(w[4*k4+3], x0.w, a0);
            a1 = fmaf(w[4*k4+0], x1.x, a1); a1 = fmaf(w[4*k4+1], x1.y, a1);
            a1 = fmaf(w[4*k4+2], x1.z, a1); a1 = fmaf(w[4*k4+3], x1.w, a1);
            a2 = fmaf(w[4*k4+0], x2.x, a2); a2 = fmaf(w[4*k4+1], x2.y, a2);
            a2 = fmaf(w[4*k4+2], x2.z, a2); a2 = fmaf(w[4*k4+3], x2.w, a2);
            a3 = fmaf(w[4*k4+0], x3.x, a3); a3 = fmaf(w[4*k4+1], x3.y, a3);
            a3 = fmaf(w[4*k4+2], x3.z, a3); a3 = fmaf(w[4*k4+3], x3.w, a3);
        }
        size_t o0 = (pbase + p0)*64 + row;
        dst[o0]     = a0;
        dst[o0+64]  = a1;
        dst[o0+128] = a2;
        dst[o0+192] = a3;
    }
}

// ---------------- dwconv, 4-pixel strips ----------------
__global__ __launch_bounds__(256) void k_pe1_s(const float* __restrict__ x,
                                               const float* __restrict__ w)
{
    __shared__ float sw[9*CC];
    for (int t = threadIdx.x; t < 9*CC; t += 256) { int c = t/9, k = t%9; sw[k*CC+c] = w[t]; }
    __syncthreads();
    int g = threadIdx.x & 15, strip = threadIdx.x >> 4;
    int pbase = blockIdx.x*64 + strip*4;
    int b = pbase >> 16, s = pbase & 65535, y = s >> 8, x0 = s & 255;
    const float4* x4 = (const float4*)x;
    const float4* sw4 = (const float4*)sw;
    float4 acc[4];
    #pragma unroll
    for (int p = 0; p < 4; p++) acc[p] = make_float4(0.f,0.f,0.f,0.f);
    size_t bb = (size_t)(b << 16);
    #pragma unroll
    for (int ky = 0; ky < 3; ky++) {
        int yy = y + ky - 1; if (yy < 0 || yy >= HH) continue;
        #pragma unroll
        for (int c = -1; c <= 4; c++) {
            int xc = x0 + c; if (xc < 0 || xc >= WWD) continue;
            float4 v = x4[(bb + (yy<<8) + xc)*16 + g];
            #pragma unroll
            for (int p = 0; p < 4; p++) {
                int kx = c - p + 1; if (kx < 0 || kx > 2) continue;
                float4 wv = sw4[(ky*3+kx)*16 + g];
                acc[p].x = fmaf(wv.x, v.x, acc[p].x); acc[p].y = fmaf(wv.y, v.y, acc[p].y);
                acc[p].z = fmaf(wv.z, v.z, acc[p].z); acc[p].w = fmaf(wv.w, v.w, acc[p].w);
            }
        }
    }
    float4* t14 = (float4*)g_t1;
    #pragma unroll
    for (int p = 0; p < 4; p++) {
        float4 r;
        r.x = geluf(acc[p].x); r.y = geluf(acc[p].y);
        r.z = geluf(acc[p].z); r.w = geluf(acc[p].w);
        t14[(size_t)(pbase+p)*16 + g] = r;
    }
}

__global__ __launch_bounds__(256) void k_pe2_s(const float* __restrict__ w)
{
    __shared__ float sw[9*CC];
    for (int t = threadIdx.x; t < 9*CC; t += 256) { int c = t/9, k = t%9; sw[k*CC+c] = w[t]; }
    __syncthreads();
    int g = threadIdx.x & 15, strip = threadIdx.x >> 4;
    int pbase = blockIdx.x*64 + strip*4;
    int b = pbase >> 16, s = pbase & 65535, y = s >> 8, x0 = s & 255;
    const float4* t14 = (const float4*)g_t1;
    const float4* sw4 = (const float4*)sw;
    float4 acc[4];
    #pragma unroll
    for (int p = 0; p < 4; p++) acc[p] = make_float4(0.f,0.f,0.f,0.f);
    size_t bb = (size_t)(b << 16);
    #pragma unroll
    for (int ky = 0; ky < 3; ky++) {
        int yy = y + ky - 1; if (yy < 0 || yy >= HH) continue;
        #pragma unroll
        for (int c = -1; c <= 4; c++) {
            int xc = x0 + c; if (xc < 0 || xc >= WWD) continue;
            float4 v = t14[(bb + (yy<<8) + xc)*16 + g];
            #pragma unroll
            for (int p = 0; p < 4; p++) {
                int kx = c - p + 1; if (kx < 0 || kx > 2) continue;
                float4 wv = sw4[(ky*3+kx)*16 + g];
                acc[p].x = fmaf(wv.x, v.x, acc[p].x); acc[p].y = fmaf(wv.y, v.y, acc[p].y);
                acc[p].z = fmaf(wv.z, v.z, acc[p].z); acc[p].w = fmaf(wv.w, v.w, acc[p].w);
            }
        }
    }
    float4* t24 = (float4*)g_t2;
    #pragma unroll
    for (int p = 0; p < 4; p++) t24[(size_t)(pbase+p)*16 + g] = acc[p];
}

__global__ __launch_bounds__(256) void k_ma_s(const float* __restrict__ dw,
                                              const float* __restrict__ dwb)
{
    __shared__ float sdw[25*CC];
    __shared__ float sdb[CC];
    for (int t = threadIdx.x; t < 25*CC; t += 256) { int c = t/25, k = t%25; sdw[k*CC+c] = dw[t]; }
    for (int t = threadIdx.x; t < CC; t += 256) sdb[t] = dwb[t];
    __syncthreads();
    int g = threadIdx.x & 15, strip = threadIdx.x >> 4;
    int pbase = blockIdx.x*64 + strip*4;
    int b = pbase >> 16, s = pbase & 65535, y = s >> 8, x0 = s & 255;
    const float4* m24 = (const float4*)g_m2;
    const float4* sdw4 = (const float4*)sdw;
    float4 bias4 = ((const float4*)sdb)[g];
    float4 acc[4];
    #pragma unroll
    for (int p = 0; p < 4; p++) acc[p] = bias4;
    size_t bb = (size_t)(b << 16);
    #pragma unroll
    for (int ky = 0; ky < 5; ky++) {
        int yy = y + ky - 2; if (yy < 0 || yy >= HH) continue;
        #pragma unroll
        for (int c = -2; c <= 5; c++) {
            int xc = x0 + c; if (xc < 0 || xc >= WWD) continue;
            float4 v = m24[(bb + (yy<<8) + xc)*16 + g];
            #pragma unroll
            for (int p = 0; p < 4; p++) {
                int kx = c - p + 2; if (kx < 0 || kx > 4) continue;
                float4 wv = sdw4[(ky*5+kx)*16 + g];
                acc[p].x = fmaf(wv.x, v.x, acc[p].x); acc[p].y = fmaf(wv.y, v.y, acc[p].y);
                acc[p].z = fmaf(wv.z, v.z, acc[p].z); acc[p].w = fmaf(wv.w, v.w, acc[p].w);
            }
        }
    }
    const float4* m14 = (const float4*)g_m1;
    const float4* v4  = (const float4*)g_v;
    float4* vm4 = (float4*)g_vm;
    #pragma unroll
    for (int p = 0; p < 4; p++) {
        size_t idx = (size_t)(pbase+p)*16 + g;
        float4 m1v = m14[idx], vv = v4[idx];
        float4 r;
        r.x = vv.x * (m1v.x * (1.f + sigmf(acc[p].x)));
        r.y = vv.y * (m1v.y * (1.f + sigmf(acc[p].y)));
        r.z = vv.z * (m1v.z * (1.f + sigmf(acc[p].z)));
        r.w = vv.w * (m1v.w * (1.f + sigmf(acc[p].w)));
        vm4[idx] = r;
    }
}

// ---------------- launcher ----------------
extern "C" void kernel_launch(void* const* d_in, const int* in_sizes, int n_in,
                              void* d_out, int out_size)
{
    const float* x_in   = (const float*)d_in[0];
    const float* mask   = (const float*)d_in[1];
    const float* Wq     = (const float*)d_in[2];
    const float* Wk     = (const float*)d_in[3];
    const float* Wv     = (const float*)d_in[4];
    const float* rescale= (const float*)d_in[5];
    const float* Wp     = (const float*)d_in[6];
    const float* bp     = (const float*)d_in[7];
    const float* mm_w1  = (const float*)d_in[8];
    const float* mm_b1  = (const float*)d_in[9];
    const float* mm_w2  = (const float*)d_in[10];
    const float* mm_b2  = (const float*)d_in[11];
    const float* mm_dw  = (const float*)d_in[12];
    const float* mm_dwb = (const float*)d_in[13];
    const float* pe_w1  = (const float*)d_in[14];
    const float* pe_w2  = (const float*)d_in[15];
    float* out = (float*)d_out;

    float *pvm, *pt2, *pwf;
    cudaGetSymbolAddress((void**)&pvm,  g_vm);
    cudaGetSymbolAddress((void**)&pt2,  g_t2);
    cudaGetSymbolAddress((void**)&pwf,  g_wfold);

    const int SM4_BYTES = (4160*3 + 1024 + 64 + 64 + 256) * 4;

    static cudaStream_t s1 = nullptr, s2 = nullptr;
    static cudaEvent_t evRoot = nullptr, evV = nullptr, evM = nullptr, evP = nullptr;
    static int init_done = 0;
    if (!init_done) {
        cudaFuncSetAttribute(k_small4, cudaFuncAttributeMaxDynamicSharedMemorySize, SM4_BYTES);
        cudaStreamCreateWithFlags(&s1, cudaStreamNonBlocking);
        cudaStreamCreateWithFlags(&s2, cudaStreamNonBlocking);
        cudaEventCreateWithFlags(&evRoot, cudaEventDisableTiming);
        cudaEventCreateWithFlags(&evV,    cudaEventDisableTiming);
        cudaEventCreateWithFlags(&evM,    cudaEventDisableTiming);
        cudaEventCreateWithFlags(&evP,    cudaEventDisableTiming);
        init_done = 1;
    }

    bool multi = (s1 && s2 && evRoot && evV && evM && evP);

    if (multi) {
        cudaEventRecord(evRoot, 0);
        cudaStreamWaitEvent(s1, evRoot, 0);
        cudaStreamWaitEvent(s2, evRoot, 0);

        // stream 0: fused gram+v, then gram chain
        k_gramv<<<NCHUNK, 256>>>(x_in, Wv);
        cudaEventRecord(evV, 0);
        k_gram_red1<<<(32*4096)/256, 256>>>();
        k_small4<<<BN, 256, SM4_BYTES>>>(Wq, Wk, Wp, rescale);

        // s1: mask path
        k_fold16<<<16, 256, 0, s1>>>(mm_w1, mm_b1, mm_w2, mm_b2);
        k_mv_dual<<<NPIX/128, 512, 0, s1>>>(mask, mm_w1, mm_b1);

        // s2: pe path
        k_pe1_s<<<NPIX/64, 256, 0, s2>>>(x_in, pe_w1);
        k_pe2_s<<<NPIX/64, 256, 0, s2>>>(pe_w2);
        cudaEventRecord(evP, s2);

        // ma on s1: needs m1, m2 (s1-ordered) and v (evV from stream 0)
        cudaStreamWaitEvent(s1, evV, 0);
        k_ma_s<<<NPIX/64, 256, 0, s1>>>(mm_dw, mm_dwb);
        cudaEventRecord(evM, s1);

        // join: final needs small4 (stream-0 ordered), ma (evM), pe2 (evP)
        cudaStreamWaitEvent(0, evM, 0);
        cudaStreamWaitEvent(0, evP, 0);
        k_mv_b<<<NPIX/128, 256>>>(pvm, pwf, bp, pt2, out, 1);
    } else {
        k_fold16<<<16, 256>>>(mm_w1, mm_b1, mm_w2, mm_b2);
        k_gramv<<<NCHUNK, 256>>>(x_in, Wv);
        k_gram_red1<<<(32*4096)/256, 256>>>();
        k_small4<<<BN, 256, SM4_BYTES>>>(Wq, Wk, Wp, rescale);
        k_mv_dual<<<NPIX/128, 512>>>(mask, mm_w1, mm_b1);
        k_pe1_s<<<NPIX/64, 256>>>(x_in, pe_w1);
        k_pe2_s<<<NPIX/64, 256>>>(pe_w2);
        k_ma_s <<<NPIX/64, 256>>>(mm_dw, mm_dwb);
        k_mv_b<<<NPIX/128, 256>>>(pvm, pwf, bp, pt2, out, 1);
    }
}